// round 2
// baseline (speedup 1.0000x reference)
#include <cuda_runtime.h>

#define NN 20000
#define NE 320000
#define NFEAT 128
#define EFEAT 32
#define HD 256
#define OUTF 128
#define NL 4
#define NG 64

#define FLAG_RELU 1
#define FLAG_ACCUM 2

// ---------------- scratch (static device globals; no allocations) ----------
__device__ float g_h0[NN * HD];
__device__ float g_h1[NN * HD];
__device__ float g_tmp[NN * HD];
__device__ float g_P[NN * HD];
__device__ float g_Q[NN * HD];
__device__ float g_agg[NN * HD];
__device__ float g_R[(size_t)NE * HD];
__device__ float g_e1[(size_t)NE * HD];
__device__ float g_pooled[NG * HD];
__device__ float g_htmp[NG * HD];
__device__ int g_starts[NG + 1];
__device__ int g_is64;   // 1 if index arrays are int64, 0 if int32

// element-indexed load honoring detected dtype
__device__ __forceinline__ long long load_idx(const void* p, long long i, int is64)
{
    if (is64) return ((const long long*)p)[i];
    return (long long)(((const int*)p)[i]);
}

// Detect whether index arrays are int64 or int32 (jax x64-disabled quirk:
// jnp.int64 silently becomes int32). If int32 data is reinterpreted as
// int64, the hi word is a random index -> value >= 2^32, out of [0, NN).
__global__ void detect_kernel(const void* ei)
{
    const long long* p = (const long long*)ei;
    int ok = 1;
#pragma unroll
    for (int i = 0; i < 8; i++) {
        long long v = p[i];
        if (v < 0 || v >= NN) ok = 0;
    }
    g_is64 = ok;
}

// ---------------- generic fp32 SGEMM: C[M,N] = A[M,K] @ B[K,N] (+bias) -----
// B row-major [K,N]. Optional: relu, accumulate into C, or atomic scatter-add
// rows into C[dstidx*N + col] where dstidx = ei[NE + row] (scatter ignores
// relu/accum). Requires: K % 8 == 0, N % 128 == 0.
__global__ void __launch_bounds__(256, 2)
sgemm(const float* __restrict__ A, const float* __restrict__ B,
      const float* __restrict__ bias, float* __restrict__ C,
      int M, int K, int N, int flags, const void* __restrict__ ei)
{
    __shared__ __align__(16) float As[8][128];
    __shared__ __align__(16) float Bs[8][128];

    const int tid = threadIdx.x;
    const int tx = tid & 15;
    const int ty = tid >> 4;
    const int bx = blockIdx.x, by = blockIdx.y;

    const int arow = tid >> 1;
    const int acol = (tid & 1) << 2;
    const int brow = tid >> 5;
    const int bcol = (tid & 31) << 2;

    const int gArow = by * 128 + arow;
    const int gBcol0 = bx * 128;

    float acc[8][8];
#pragma unroll
    for (int i = 0; i < 8; i++)
#pragma unroll
        for (int j = 0; j < 8; j++) acc[i][j] = 0.f;

    const float* Ap = A + (size_t)gArow * K;
    const float* Bp = B + (size_t)brow * N + gBcol0 + bcol;

    for (int kt = 0; kt < K; kt += 8) {
        float4 av = make_float4(0.f, 0.f, 0.f, 0.f);
        if (gArow < M) av = *(const float4*)(Ap + kt + acol);
        As[acol + 0][arow] = av.x;
        As[acol + 1][arow] = av.y;
        As[acol + 2][arow] = av.z;
        As[acol + 3][arow] = av.w;

        float4 bv = *(const float4*)(Bp + (size_t)kt * N);
        *(float4*)&Bs[brow][bcol] = bv;
        __syncthreads();

#pragma unroll
        for (int k = 0; k < 8; k++) {
            float4 a0 = *(const float4*)&As[k][ty * 8];
            float4 a1 = *(const float4*)&As[k][ty * 8 + 4];
            float4 b0 = *(const float4*)&Bs[k][tx * 4];
            float4 b1 = *(const float4*)&Bs[k][64 + tx * 4];
            float a[8] = {a0.x, a0.y, a0.z, a0.w, a1.x, a1.y, a1.z, a1.w};
            float b[8] = {b0.x, b0.y, b0.z, b0.w, b1.x, b1.y, b1.z, b1.w};
#pragma unroll
            for (int i = 0; i < 8; i++)
#pragma unroll
                for (int j = 0; j < 8; j++)
                    acc[i][j] = fmaf(a[i], b[j], acc[i][j]);
        }
        __syncthreads();
    }

    const bool relu = (flags & FLAG_RELU) != 0;
    const bool accum = (flags & FLAG_ACCUM) != 0;

    float bb[8];
#pragma unroll
    for (int j = 0; j < 8; j++) {
        int col = gBcol0 + ((j < 4) ? (tx * 4 + j) : (64 + tx * 4 + (j - 4)));
        bb[j] = bias ? bias[col] : 0.f;
    }

    const int is64 = ei ? g_is64 : 0;

#pragma unroll
    for (int i = 0; i < 8; i++) {
        int row = by * 128 + ty * 8 + i;
        if (row >= M) continue;
        if (ei) {
            long long t = load_idx(ei, (long long)NE + row, is64);  // dst[row]
            size_t base = (size_t)t * N;
#pragma unroll
            for (int j = 0; j < 8; j++) {
                int col = gBcol0 + ((j < 4) ? (tx * 4 + j) : (64 + tx * 4 + (j - 4)));
                atomicAdd(&C[base + col], acc[i][j] + bb[j]);
            }
        } else {
            size_t base = (size_t)row * N;
            int c0 = gBcol0 + tx * 4;
            int c1 = gBcol0 + 64 + tx * 4;
            float4 v0 = make_float4(acc[i][0] + bb[0], acc[i][1] + bb[1],
                                    acc[i][2] + bb[2], acc[i][3] + bb[3]);
            float4 v1 = make_float4(acc[i][4] + bb[4], acc[i][5] + bb[5],
                                    acc[i][6] + bb[6], acc[i][7] + bb[7]);
            if (accum) {
                float4 o0 = *(const float4*)&C[base + c0];
                float4 o1 = *(const float4*)&C[base + c1];
                v0.x += o0.x; v0.y += o0.y; v0.z += o0.z; v0.w += o0.w;
                v1.x += o1.x; v1.y += o1.y; v1.z += o1.z; v1.w += o1.w;
            }
            if (relu) {
                v0.x = fmaxf(v0.x, 0.f); v0.y = fmaxf(v0.y, 0.f);
                v0.z = fmaxf(v0.z, 0.f); v0.w = fmaxf(v0.w, 0.f);
                v1.x = fmaxf(v1.x, 0.f); v1.y = fmaxf(v1.y, 0.f);
                v1.z = fmaxf(v1.z, 0.f); v1.w = fmaxf(v1.w, 0.f);
            }
            *(float4*)&C[base + c0] = v0;
            *(float4*)&C[base + c1] = v1;
        }
    }
}

// ---------------- per-edge combine: e1 = relu(P[dst]+Q[src]+R+b1) ----------
// src[e] = ei[e], dst[e] = ei[NE + e]
__global__ void combine_kernel(const float* __restrict__ P, const float* __restrict__ Q,
                               const float* __restrict__ R, const float* __restrict__ b1,
                               const void* __restrict__ ei,
                               float* __restrict__ e1)
{
    int e = blockIdx.x * 4 + (threadIdx.x >> 6);
    if (e >= NE) return;
    int is64 = g_is64;
    int c = (threadIdx.x & 63) << 2;
    int s = (int)load_idx(ei, e, is64);
    int d = (int)load_idx(ei, (long long)NE + e, is64);
    float4 p = *(const float4*)(P + (size_t)d * HD + c);
    float4 q = *(const float4*)(Q + (size_t)s * HD + c);
    float4 r = *(const float4*)(R + (size_t)e * HD + c);
    float4 b = *(const float4*)(b1 + c);
    float4 o;
    o.x = fmaxf(p.x + q.x + r.x + b.x, 0.f);
    o.y = fmaxf(p.y + q.y + r.y + b.y, 0.f);
    o.z = fmaxf(p.z + q.z + r.z + b.z, 0.f);
    o.w = fmaxf(p.w + q.w + r.w + b.w, 0.f);
    *(float4*)(e1 + (size_t)e * HD + c) = o;
}

__global__ void zero_kernel(float* __restrict__ p, int n)
{
    int i = blockIdx.x * blockDim.x + threadIdx.x;
    if (i < n) p[i] = 0.f;
}

// ---------------- pooling -------------------------------------------------
__global__ void starts_kernel(const void* __restrict__ batch)
{
    int g = threadIdx.x;
    if (g > NG) return;
    int is64 = g_is64;
    int lo = 0, hi = NN;
    while (lo < hi) {
        int mid = (lo + hi) >> 1;
        if (load_idx(batch, mid, is64) < (long long)g) lo = mid + 1;
        else hi = mid;
    }
    g_starts[g] = lo;
}

__global__ void pool_kernel(const float* __restrict__ h)
{
    int g = blockIdx.x;
    int c = threadIdx.x;  // 256
    int s = g_starts[g], e = g_starts[g + 1];
    float sum = 0.f;
    for (int i = s; i < e; i++) sum += h[(size_t)i * HD + c];
    float cnt = (float)(e - s);
    g_pooled[g * HD + c] = sum / fmaxf(cnt, 1.f);
}

// ---------------- driver --------------------------------------------------
extern "C" void kernel_launch(void* const* d_in, const int* in_sizes, int n_in,
                              void* d_out, int out_size)
{
    const float* x        = (const float*)d_in[0];
    const float* edge_attr= (const float*)d_in[1];
    const float* emb_w1   = (const float*)d_in[2];
    const float* emb_b1   = (const float*)d_in[3];
    const float* emb_w2   = (const float*)d_in[4];
    const float* emb_b2   = (const float*)d_in[5];
    const float* mw1      = (const float*)d_in[6];
    const float* mb1      = (const float*)d_in[7];
    const float* mw2      = (const float*)d_in[8];
    const float* mb2      = (const float*)d_in[9];
    const float* uw1      = (const float*)d_in[10];
    const float* ub1      = (const float*)d_in[11];
    const float* uw2      = (const float*)d_in[12];
    const float* ub2      = (const float*)d_in[13];
    const float* hw1      = (const float*)d_in[14];
    const float* hb1      = (const float*)d_in[15];
    const float* hw2      = (const float*)d_in[16];
    const float* hb2      = (const float*)d_in[17];
    const void* ei        = d_in[18];
    const void* batch     = d_in[19];

    float *h0, *h1, *tmp, *P, *Q, *R, *e1, *agg, *pooled, *htmp;
    cudaGetSymbolAddress((void**)&h0, g_h0);
    cudaGetSymbolAddress((void**)&h1, g_h1);
    cudaGetSymbolAddress((void**)&tmp, g_tmp);
    cudaGetSymbolAddress((void**)&P, g_P);
    cudaGetSymbolAddress((void**)&Q, g_Q);
    cudaGetSymbolAddress((void**)&R, g_R);
    cudaGetSymbolAddress((void**)&e1, g_e1);
    cudaGetSymbolAddress((void**)&agg, g_agg);
    cudaGetSymbolAddress((void**)&pooled, g_pooled);
    cudaGetSymbolAddress((void**)&htmp, g_htmp);

    detect_kernel<<<1, 1>>>(ei);

    dim3 blk(256);
    dim3 gN(HD / 128, (NN + 127) / 128);   // node-sized GEMMs, N=256
    dim3 gE(HD / 128, NE / 128);           // edge-sized GEMMs, N=256

    // Embedder: h = relu(x@W1+b1)@W2+b2
    sgemm<<<gN, blk>>>(x, emb_w1, emb_b1, tmp, NN, NFEAT, HD, FLAG_RELU, nullptr);
    sgemm<<<gN, blk>>>(tmp, emb_w2, emb_b2, h0, NN, HD, HD, 0, nullptr);

    float* cur = h0;
    float* nxt = h1;
    for (int l = 0; l < NL; l++) {
        const float* w1 = mw1 + (size_t)l * (2 * HD + EFEAT) * HD;
        // Linearity split of message layer 1: pre-relu = P[dst] + Q[src] + R[e] + b1
        sgemm<<<gN, blk>>>(cur, w1, nullptr, P, NN, HD, HD, 0, nullptr);
        sgemm<<<gN, blk>>>(cur, w1 + (size_t)HD * HD, nullptr, Q, NN, HD, HD, 0, nullptr);
        sgemm<<<gE, blk>>>(edge_attr, w1 + (size_t)2 * HD * HD, nullptr, R, NE, EFEAT, HD, 0, nullptr);
        combine_kernel<<<NE / 4, 256>>>(P, Q, R, mb1 + (size_t)l * HD, ei, e1);
        // Message layer 2 fused with scatter-add into agg
        zero_kernel<<<(NN * HD + 1023) / 1024, 1024>>>(agg, NN * HD);
        sgemm<<<gE, blk>>>(e1, mw2 + (size_t)l * HD * HD, mb2 + (size_t)l * HD,
                           agg, NE, HD, HD, 0, ei);
        // Update MLP: concat(h, agg) split into two accumulating GEMMs
        sgemm<<<gN, blk>>>(cur, uw1 + (size_t)l * 2 * HD * HD, ub1 + (size_t)l * HD,
                           tmp, NN, HD, HD, 0, nullptr);
        sgemm<<<gN, blk>>>(agg, uw1 + (size_t)l * 2 * HD * HD + (size_t)HD * HD, nullptr,
                           tmp, NN, HD, HD, FLAG_ACCUM | FLAG_RELU, nullptr);
        sgemm<<<gN, blk>>>(tmp, uw2 + (size_t)l * HD * HD, ub2 + (size_t)l * HD,
                           nxt, NN, HD, HD, 0, nullptr);
        float* t = cur; cur = nxt; nxt = t;
    }

    // Pool + head
    starts_kernel<<<1, 128>>>(batch);
    pool_kernel<<<NG, HD>>>(cur);
    sgemm<<<dim3(2, 1), blk>>>(pooled, hw1, hb1, htmp, NG, HD, HD, FLAG_RELU, nullptr);
    sgemm<<<dim3(1, 1), blk>>>(htmp, hw2, hb2, (float*)d_out, NG, HD, OUTF, 0, nullptr);
}

// round 3
// speedup vs baseline: 1.4527x; 1.4527x over previous
#include <cuda_runtime.h>

#define NN 20000
#define NE 320000
#define NFEAT 128
#define EFEAT 32
#define HD 256
#define OUTF 128
#define NL 4
#define NG 64

#define FLAG_RELU 1
#define FLAG_ACCUM 2

// ---------------- scratch (static device globals; no allocations) ----------
__device__ float g_h0[NN * HD];
__device__ float g_h1[NN * HD];
__device__ float g_tmp[NN * HD];
__device__ float g_PQ[NN * 2 * HD];     // [n][0:256]=P, [n][256:512]=Q
__device__ float g_S[NN * HD];          // scatter-accumulated relu messages
__device__ float g_agg[NN * HD];
__device__ float g_Bcat[HD * 2 * HD];   // repacked [256,512] weight for PQ GEMM
__device__ float g_deg[NN];
__device__ float g_pooled[NG * HD];
__device__ float g_htmp[NG * HD];
__device__ int g_starts[NG + 1];
__device__ int g_is64;   // 1 if index arrays are int64, 0 if int32

// element-indexed load honoring detected dtype
__device__ __forceinline__ long long load_idx(const void* p, long long i, int is64)
{
    if (is64) return ((const long long*)p)[i];
    return (long long)(((const int*)p)[i]);
}

// Detect whether index arrays are int64 or int32 (jax x64-disabled quirk).
__global__ void detect_kernel(const void* ei)
{
    const long long* p = (const long long*)ei;
    int ok = 1;
#pragma unroll
    for (int i = 0; i < 8; i++) {
        long long v = p[i];
        if (v < 0 || v >= NN) ok = 0;
    }
    g_is64 = ok;
}

// ---------------- generic fp32 SGEMM: C[M,N] = A[M,K] @ B[K,N] -------------
// B row-major [K,N]. Epilogue options:
//   bias + relu/accum, or per-row-scaled bias (deg != nullptr):
//   C = A@B + deg[row]*bias[col]
// Requires: K % 8 == 0, N % 128 == 0.
__global__ void __launch_bounds__(256, 2)
sgemm(const float* __restrict__ A, const float* __restrict__ B,
      const float* __restrict__ bias, float* __restrict__ C,
      int M, int K, int N, int flags, const float* __restrict__ deg)
{
    __shared__ __align__(16) float As[8][128];
    __shared__ __align__(16) float Bs[8][128];

    const int tid = threadIdx.x;
    const int tx = tid & 15;
    const int ty = tid >> 4;
    const int bx = blockIdx.x, by = blockIdx.y;

    const int arow = tid >> 1;
    const int acol = (tid & 1) << 2;
    const int brow = tid >> 5;
    const int bcol = (tid & 31) << 2;

    const int gArow = by * 128 + arow;
    const int gBcol0 = bx * 128;

    float acc[8][8];
#pragma unroll
    for (int i = 0; i < 8; i++)
#pragma unroll
        for (int j = 0; j < 8; j++) acc[i][j] = 0.f;

    const float* Ap = A + (size_t)gArow * K;
    const float* Bp = B + (size_t)brow * N + gBcol0 + bcol;

    for (int kt = 0; kt < K; kt += 8) {
        float4 av = make_float4(0.f, 0.f, 0.f, 0.f);
        if (gArow < M) av = *(const float4*)(Ap + kt + acol);
        As[acol + 0][arow] = av.x;
        As[acol + 1][arow] = av.y;
        As[acol + 2][arow] = av.z;
        As[acol + 3][arow] = av.w;

        float4 bv = *(const float4*)(Bp + (size_t)kt * N);
        *(float4*)&Bs[brow][bcol] = bv;
        __syncthreads();

#pragma unroll
        for (int k = 0; k < 8; k++) {
            float4 a0 = *(const float4*)&As[k][ty * 8];
            float4 a1 = *(const float4*)&As[k][ty * 8 + 4];
            float4 b0 = *(const float4*)&Bs[k][tx * 4];
            float4 b1 = *(const float4*)&Bs[k][64 + tx * 4];
            float a[8] = {a0.x, a0.y, a0.z, a0.w, a1.x, a1.y, a1.z, a1.w};
            float b[8] = {b0.x, b0.y, b0.z, b0.w, b1.x, b1.y, b1.z, b1.w};
#pragma unroll
            for (int i = 0; i < 8; i++)
#pragma unroll
                for (int j = 0; j < 8; j++)
                    acc[i][j] = fmaf(a[i], b[j], acc[i][j]);
        }
        __syncthreads();
    }

    const bool relu = (flags & FLAG_RELU) != 0;
    const bool accum = (flags & FLAG_ACCUM) != 0;

    float bb[8];
#pragma unroll
    for (int j = 0; j < 8; j++) {
        int col = gBcol0 + ((j < 4) ? (tx * 4 + j) : (64 + tx * 4 + (j - 4)));
        bb[j] = bias ? bias[col] : 0.f;
    }

#pragma unroll
    for (int i = 0; i < 8; i++) {
        int row = by * 128 + ty * 8 + i;
        if (row >= M) continue;
        float bscale = deg ? deg[row] : 1.f;
        size_t base = (size_t)row * N;
        int c0 = gBcol0 + tx * 4;
        int c1 = gBcol0 + 64 + tx * 4;
        float4 v0 = make_float4(acc[i][0] + bscale * bb[0], acc[i][1] + bscale * bb[1],
                                acc[i][2] + bscale * bb[2], acc[i][3] + bscale * bb[3]);
        float4 v1 = make_float4(acc[i][4] + bscale * bb[4], acc[i][5] + bscale * bb[5],
                                acc[i][6] + bscale * bb[6], acc[i][7] + bscale * bb[7]);
        if (accum) {
            float4 o0 = *(const float4*)&C[base + c0];
            float4 o1 = *(const float4*)&C[base + c1];
            v0.x += o0.x; v0.y += o0.y; v0.z += o0.z; v0.w += o0.w;
            v1.x += o1.x; v1.y += o1.y; v1.z += o1.z; v1.w += o1.w;
        }
        if (relu) {
            v0.x = fmaxf(v0.x, 0.f); v0.y = fmaxf(v0.y, 0.f);
            v0.z = fmaxf(v0.z, 0.f); v0.w = fmaxf(v0.w, 0.f);
            v1.x = fmaxf(v1.x, 0.f); v1.y = fmaxf(v1.y, 0.f);
            v1.z = fmaxf(v1.z, 0.f); v1.w = fmaxf(v1.w, 0.f);
        }
        *(float4*)&C[base + c0] = v0;
        *(float4*)&C[base + c1] = v1;
    }
}

// ---------------- repack W1 P|Q columns into Bcat[256][512] ----------------
// Bcat[k][j] = w1[k][j] for j<256, w1[256+k][j-256] for j>=256
__global__ void repack_kernel(const float* __restrict__ w1, float* __restrict__ Bcat)
{
    int idx = blockIdx.x * 256 + threadIdx.x;   // over 256*512
    if (idx >= HD * 2 * HD) return;
    int k = idx >> 9;          // /512
    int j = idx & 511;
    float v = (j < HD) ? w1[(size_t)k * HD + j]
                       : w1[(size_t)(HD + k) * HD + (j - HD)];
    Bcat[idx] = v;
}

// ---------------- combine + fused R-GEMM + scatter into S ------------------
// per edge e: e1 = relu(P[dst] + Q[src] + edge_attr[e]@W1c + b1)
//             atomicAdd(S[dst], e1)
// 4 edges per 256-thread block; 64 threads per edge, 4 cols each.
__global__ void __launch_bounds__(256)
combine_scatter(const float* __restrict__ PQ, const float* __restrict__ ea,
                const float* __restrict__ W1c, const float* __restrict__ b1,
                const void* __restrict__ ei, float* __restrict__ S)
{
    __shared__ __align__(16) float sW[EFEAT * HD];   // 32KB
    __shared__ float sB[HD];

    const int tid = threadIdx.x;
    for (int i = tid; i < EFEAT * HD; i += 256) sW[i] = W1c[i];
    if (tid < HD) sB[tid] = b1[tid];
    // 256 < HD? HD=256 so one pass covers; guard anyway
    __syncthreads();

    int e = blockIdx.x * 4 + (tid >> 6);
    if (e >= NE) return;
    const int is64 = g_is64;
    const int c = (tid & 63) << 2;
    const int s = (int)load_idx(ei, e, is64);
    const int d = (int)load_idx(ei, (long long)NE + e, is64);

    float4 p = *(const float4*)(PQ + (size_t)d * (2 * HD) + c);
    float4 q = *(const float4*)(PQ + (size_t)s * (2 * HD) + HD + c);

    // r = edge_attr[e] @ W1c  (K=32)
    float r0 = 0.f, r1 = 0.f, r2 = 0.f, r3 = 0.f;
    const float* eap = ea + (size_t)e * EFEAT;
#pragma unroll
    for (int k = 0; k < EFEAT; k++) {
        float a = eap[k];                 // uniform across the 64 threads
        float4 w = *(const float4*)&sW[k * HD + c];
        r0 = fmaf(a, w.x, r0);
        r1 = fmaf(a, w.y, r1);
        r2 = fmaf(a, w.z, r2);
        r3 = fmaf(a, w.w, r3);
    }

    float v0 = fmaxf(p.x + q.x + r0 + sB[c + 0], 0.f);
    float v1 = fmaxf(p.y + q.y + r1 + sB[c + 1], 0.f);
    float v2 = fmaxf(p.z + q.z + r2 + sB[c + 2], 0.f);
    float v3 = fmaxf(p.w + q.w + r3 + sB[c + 3], 0.f);

    float* Sd = S + (size_t)d * HD + c;
    atomicAdd(Sd + 0, v0);
    atomicAdd(Sd + 1, v1);
    atomicAdd(Sd + 2, v2);
    atomicAdd(Sd + 3, v3);
}

__global__ void zero_kernel(float* __restrict__ p, int n)
{
    int i = blockIdx.x * blockDim.x + threadIdx.x;
    if (i < n) p[i] = 0.f;
}

// ---------------- degree (once) -------------------------------------------
__global__ void deg_kernel(const void* __restrict__ ei, float* __restrict__ deg)
{
    int e = blockIdx.x * 256 + threadIdx.x;
    if (e >= NE) return;
    int d = (int)load_idx(ei, (long long)NE + e, g_is64);
    atomicAdd(&deg[d], 1.f);
}

// ---------------- pooling -------------------------------------------------
__global__ void starts_kernel(const void* __restrict__ batch)
{
    int g = threadIdx.x;
    if (g > NG) return;
    int is64 = g_is64;
    int lo = 0, hi = NN;
    while (lo < hi) {
        int mid = (lo + hi) >> 1;
        if (load_idx(batch, mid, is64) < (long long)g) lo = mid + 1;
        else hi = mid;
    }
    g_starts[g] = lo;
}

__global__ void pool_kernel(const float* __restrict__ h)
{
    int g = blockIdx.x;
    int c = threadIdx.x;  // 256
    int s = g_starts[g], e = g_starts[g + 1];
    float sum = 0.f;
    for (int i = s; i < e; i++) sum += h[(size_t)i * HD + c];
    float cnt = (float)(e - s);
    g_pooled[g * HD + c] = sum / fmaxf(cnt, 1.f);
}

// ---------------- driver --------------------------------------------------
extern "C" void kernel_launch(void* const* d_in, const int* in_sizes, int n_in,
                              void* d_out, int out_size)
{
    const float* x        = (const float*)d_in[0];
    const float* edge_attr= (const float*)d_in[1];
    const float* emb_w1   = (const float*)d_in[2];
    const float* emb_b1   = (const float*)d_in[3];
    const float* emb_w2   = (const float*)d_in[4];
    const float* emb_b2   = (const float*)d_in[5];
    const float* mw1      = (const float*)d_in[6];
    const float* mb1      = (const float*)d_in[7];
    const float* mw2      = (const float*)d_in[8];
    const float* mb2      = (const float*)d_in[9];
    const float* uw1      = (const float*)d_in[10];
    const float* ub1      = (const float*)d_in[11];
    const float* uw2      = (const float*)d_in[12];
    const float* ub2      = (const float*)d_in[13];
    const float* hw1      = (const float*)d_in[14];
    const float* hb1      = (const float*)d_in[15];
    const float* hw2      = (const float*)d_in[16];
    const float* hb2      = (const float*)d_in[17];
    const void* ei        = d_in[18];
    const void* batch     = d_in[19];

    float *h0, *h1, *tmp, *PQ, *S, *agg, *Bcat, *deg, *pooled, *htmp;
    cudaGetSymbolAddress((void**)&h0, g_h0);
    cudaGetSymbolAddress((void**)&h1, g_h1);
    cudaGetSymbolAddress((void**)&tmp, g_tmp);
    cudaGetSymbolAddress((void**)&PQ, g_PQ);
    cudaGetSymbolAddress((void**)&S, g_S);
    cudaGetSymbolAddress((void**)&agg, g_agg);
    cudaGetSymbolAddress((void**)&Bcat, g_Bcat);
    cudaGetSymbolAddress((void**)&deg, g_deg);
    cudaGetSymbolAddress((void**)&pooled, g_pooled);
    cudaGetSymbolAddress((void**)&htmp, g_htmp);

    detect_kernel<<<1, 1>>>(ei);
    zero_kernel<<<(NN + 1023) / 1024, 1024>>>(deg, NN);
    deg_kernel<<<(NE + 255) / 256, 256>>>(ei, deg);

    dim3 blk(256);
    dim3 gN(HD / 128, (NN + 127) / 128);      // [*,256] node GEMMs
    dim3 gPQ(2 * HD / 128, (NN + 127) / 128); // [*,512] PQ GEMM

    // Embedder: h = relu(x@W1+b1)@W2+b2
    sgemm<<<gN, blk>>>(x, emb_w1, emb_b1, tmp, NN, NFEAT, HD, FLAG_RELU, nullptr);
    sgemm<<<gN, blk>>>(tmp, emb_w2, emb_b2, h0, NN, HD, HD, 0, nullptr);

    float* cur = h0;
    float* nxt = h1;
    for (int l = 0; l < NL; l++) {
        const float* w1 = mw1 + (size_t)l * (2 * HD + EFEAT) * HD;
        // Repack [W1a | W1b] into Bcat[256,512], then PQ = h @ Bcat
        repack_kernel<<<(HD * 2 * HD + 255) / 256, 256>>>(w1, Bcat);
        sgemm<<<gPQ, blk>>>(cur, Bcat, nullptr, PQ, NN, HD, 2 * HD, 0, nullptr);
        // S = scatter_add over edges of relu(P[dst]+Q[src]+ea@W1c+b1)
        zero_kernel<<<(NN * HD + 1023) / 1024, 1024>>>(S, NN * HD);
        combine_scatter<<<NE / 4, 256>>>(PQ, edge_attr, w1 + (size_t)2 * HD * HD,
                                         mb1 + (size_t)l * HD, ei, S);
        // agg = S @ W2 + deg*b2   (linearity of the post-relu layer)
        sgemm<<<gN, blk>>>(S, mw2 + (size_t)l * HD * HD, mb2 + (size_t)l * HD,
                           agg, NN, HD, HD, 0, deg);
        // Update MLP: tmp = relu(h@Uw1a + agg@Uw1b + ub1); h_new = tmp@Uw2+ub2
        sgemm<<<gN, blk>>>(cur, uw1 + (size_t)l * 2 * HD * HD, ub1 + (size_t)l * HD,
                           tmp, NN, HD, HD, 0, nullptr);
        sgemm<<<gN, blk>>>(agg, uw1 + (size_t)l * 2 * HD * HD + (size_t)HD * HD, nullptr,
                           tmp, NN, HD, HD, FLAG_ACCUM | FLAG_RELU, nullptr);
        sgemm<<<gN, blk>>>(tmp, uw2 + (size_t)l * HD * HD, ub2 + (size_t)l * HD,
                           nxt, NN, HD, HD, 0, nullptr);
        float* t = cur; cur = nxt; nxt = t;
    }

    // Pool + head
    starts_kernel<<<1, 128>>>(batch);
    pool_kernel<<<NG, HD>>>(cur);
    sgemm<<<dim3(2, 1), blk>>>(pooled, hw1, hb1, htmp, NG, HD, HD, FLAG_RELU, nullptr);
    sgemm<<<dim3(1, 1), blk>>>(htmp, hw2, hb2, (float*)d_out, NG, HD, OUTF, 0, nullptr);
}

// round 4
// speedup vs baseline: 1.5138x; 1.0421x over previous
#include <cuda_runtime.h>

#define NN 20000
#define NE 320000
#define NFEAT 128
#define EFEAT 32
#define HD 256
#define OUTF 128
#define NL 4
#define NG 64

#define FLAG_RELU 1

// ---------------- scratch (static device globals; no allocations) ----------
__device__ float g_cat0[NN * 2 * HD];   // [n][0:256]=h, [n][256:512]=agg
__device__ float g_cat1[NN * 2 * HD];
__device__ float g_tmp[NN * HD];
__device__ float g_PQ[NN * 2 * HD];     // [n][0:256]=P, [n][256:512]=Q
__device__ float g_S[NN * HD];          // scatter-accumulated relu messages
__device__ float g_Bcat[HD * 2 * HD];   // repacked [256,512] weight for PQ GEMM
__device__ float g_deg[NN];
__device__ float g_pooled[NG * HD];
__device__ float g_htmp[NG * HD];
__device__ int g_starts[NG + 1];
__device__ int g_is64;   // 1 if index arrays are int64, 0 if int32

// element-indexed load honoring detected dtype
__device__ __forceinline__ long long load_idx(const void* p, long long i, int is64)
{
    if (is64) return ((const long long*)p)[i];
    return (long long)(((const int*)p)[i]);
}

// Detect whether index arrays are int64 or int32 (jax x64-disabled quirk).
__global__ void detect_kernel(const void* ei)
{
    const long long* p = (const long long*)ei;
    int ok = 1;
#pragma unroll
    for (int i = 0; i < 8; i++) {
        long long v = p[i];
        if (v < 0 || v >= NN) ok = 0;
    }
    g_is64 = ok;
}

// ---------------- generic fp32 SGEMM: C[M,N] = A[M,K] @ B[K,N] -------------
// A row stride = lda, C row stride = ldc, B row-major [K,N] contiguous.
// Epilogue: +bias (optionally scaled per-row by deg), optional relu.
// Requires: K % 8 == 0, N % 128 == 0, lda/ldc % 4 == 0.
__global__ void __launch_bounds__(256, 2)
sgemm(const float* __restrict__ A, int lda,
      const float* __restrict__ B,
      const float* __restrict__ bias, float* __restrict__ C, int ldc,
      int M, int K, int N, int flags, const float* __restrict__ deg)
{
    __shared__ __align__(16) float As[8][128];
    __shared__ __align__(16) float Bs[8][128];

    const int tid = threadIdx.x;
    const int tx = tid & 15;
    const int ty = tid >> 4;
    const int bx = blockIdx.x, by = blockIdx.y;

    const int arow = tid >> 1;
    const int acol = (tid & 1) << 2;
    const int brow = tid >> 5;
    const int bcol = (tid & 31) << 2;

    const int gArow = by * 128 + arow;
    const int gBcol0 = bx * 128;

    float acc[8][8];
#pragma unroll
    for (int i = 0; i < 8; i++)
#pragma unroll
        for (int j = 0; j < 8; j++) acc[i][j] = 0.f;

    const float* Ap = A + (size_t)gArow * lda;
    const float* Bp = B + (size_t)brow * N + gBcol0 + bcol;

    for (int kt = 0; kt < K; kt += 8) {
        float4 av = make_float4(0.f, 0.f, 0.f, 0.f);
        if (gArow < M) av = *(const float4*)(Ap + kt + acol);
        As[acol + 0][arow] = av.x;
        As[acol + 1][arow] = av.y;
        As[acol + 2][arow] = av.z;
        As[acol + 3][arow] = av.w;

        float4 bv = *(const float4*)(Bp + (size_t)kt * N);
        *(float4*)&Bs[brow][bcol] = bv;
        __syncthreads();

#pragma unroll
        for (int k = 0; k < 8; k++) {
            float4 a0 = *(const float4*)&As[k][ty * 8];
            float4 a1 = *(const float4*)&As[k][ty * 8 + 4];
            float4 b0 = *(const float4*)&Bs[k][tx * 4];
            float4 b1 = *(const float4*)&Bs[k][64 + tx * 4];
            float a[8] = {a0.x, a0.y, a0.z, a0.w, a1.x, a1.y, a1.z, a1.w};
            float b[8] = {b0.x, b0.y, b0.z, b0.w, b1.x, b1.y, b1.z, b1.w};
#pragma unroll
            for (int i = 0; i < 8; i++)
#pragma unroll
                for (int j = 0; j < 8; j++)
                    acc[i][j] = fmaf(a[i], b[j], acc[i][j]);
        }
        __syncthreads();
    }

    const bool relu = (flags & FLAG_RELU) != 0;

    float bb[8];
#pragma unroll
    for (int j = 0; j < 8; j++) {
        int col = gBcol0 + ((j < 4) ? (tx * 4 + j) : (64 + tx * 4 + (j - 4)));
        bb[j] = bias ? bias[col] : 0.f;
    }

#pragma unroll
    for (int i = 0; i < 8; i++) {
        int row = by * 128 + ty * 8 + i;
        if (row >= M) continue;
        float bscale = deg ? deg[row] : 1.f;
        size_t base = (size_t)row * ldc;
        int c0 = gBcol0 + tx * 4;
        int c1 = gBcol0 + 64 + tx * 4;
        float4 v0 = make_float4(acc[i][0] + bscale * bb[0], acc[i][1] + bscale * bb[1],
                                acc[i][2] + bscale * bb[2], acc[i][3] + bscale * bb[3]);
        float4 v1 = make_float4(acc[i][4] + bscale * bb[4], acc[i][5] + bscale * bb[5],
                                acc[i][6] + bscale * bb[6], acc[i][7] + bscale * bb[7]);
        if (relu) {
            v0.x = fmaxf(v0.x, 0.f); v0.y = fmaxf(v0.y, 0.f);
            v0.z = fmaxf(v0.z, 0.f); v0.w = fmaxf(v0.w, 0.f);
            v1.x = fmaxf(v1.x, 0.f); v1.y = fmaxf(v1.y, 0.f);
            v1.z = fmaxf(v1.z, 0.f); v1.w = fmaxf(v1.w, 0.f);
        }
        *(float4*)&C[base + c0] = v0;
        *(float4*)&C[base + c1] = v1;
    }
}

// ---------------- repack W1 P|Q columns into Bcat[256][512] ----------------
__global__ void repack_kernel(const float* __restrict__ w1, float* __restrict__ Bcat)
{
    int idx = blockIdx.x * 256 + threadIdx.x;   // over 256*512
    if (idx >= HD * 2 * HD) return;
    int k = idx >> 9;
    int j = idx & 511;
    float v = (j < HD) ? w1[(size_t)k * HD + j]
                       : w1[(size_t)(HD + k) * HD + (j - HD)];
    Bcat[idx] = v;
}

// ---------------- combine + fused R-GEMM + vector-red scatter into S -------
// per edge e: e1 = relu(P[dst] + Q[src] + edge_attr[e]@W1c + b1)
//             red.v4 S[dst] += e1
__global__ void __launch_bounds__(256)
combine_scatter(const float* __restrict__ PQ, const float* __restrict__ ea,
                const float* __restrict__ W1c, const float* __restrict__ b1,
                const void* __restrict__ ei, float* __restrict__ S)
{
    __shared__ __align__(16) float sW[EFEAT * HD];   // 32KB
    __shared__ float sB[HD];

    const int tid = threadIdx.x;
    for (int i = tid; i < EFEAT * HD; i += 256) sW[i] = W1c[i];
    if (tid < HD) sB[tid] = b1[tid];
    __syncthreads();

    int e = blockIdx.x * 4 + (tid >> 6);
    if (e >= NE) return;
    const int is64 = g_is64;
    const int c = (tid & 63) << 2;
    const int s = (int)load_idx(ei, e, is64);
    const int d = (int)load_idx(ei, (long long)NE + e, is64);

    float4 p = *(const float4*)(PQ + (size_t)d * (2 * HD) + c);
    float4 q = *(const float4*)(PQ + (size_t)s * (2 * HD) + HD + c);

    // r = edge_attr[e] @ W1c  (K=32); ea row is uniform across the 64 threads
    float r0 = 0.f, r1 = 0.f, r2 = 0.f, r3 = 0.f;
    const float* eap = ea + (size_t)e * EFEAT;
#pragma unroll
    for (int k = 0; k < EFEAT; k++) {
        float a = eap[k];
        float4 w = *(const float4*)&sW[k * HD + c];
        r0 = fmaf(a, w.x, r0);
        r1 = fmaf(a, w.y, r1);
        r2 = fmaf(a, w.z, r2);
        r3 = fmaf(a, w.w, r3);
    }

    float v0 = fmaxf(p.x + q.x + r0 + sB[c + 0], 0.f);
    float v1 = fmaxf(p.y + q.y + r1 + sB[c + 1], 0.f);
    float v2 = fmaxf(p.z + q.z + r2 + sB[c + 2], 0.f);
    float v3 = fmaxf(p.w + q.w + r3 + sB[c + 3], 0.f);

    float* Sd = S + (size_t)d * HD + c;
    asm volatile("red.global.add.v4.f32 [%0], {%1, %2, %3, %4};"
                 :: "l"(Sd), "f"(v0), "f"(v1), "f"(v2), "f"(v3) : "memory");
}

__global__ void zero_kernel(float* __restrict__ p, int n)
{
    int i = blockIdx.x * blockDim.x + threadIdx.x;
    if (i < n) p[i] = 0.f;
}

// ---------------- degree (once) -------------------------------------------
__global__ void deg_kernel(const void* __restrict__ ei, float* __restrict__ deg)
{
    int e = blockIdx.x * 256 + threadIdx.x;
    if (e >= NE) return;
    int d = (int)load_idx(ei, (long long)NE + e, g_is64);
    atomicAdd(&deg[d], 1.f);
}

// ---------------- pooling -------------------------------------------------
__global__ void starts_kernel(const void* __restrict__ batch)
{
    int g = threadIdx.x;
    if (g > NG) return;
    int is64 = g_is64;
    int lo = 0, hi = NN;
    while (lo < hi) {
        int mid = (lo + hi) >> 1;
        if (load_idx(batch, mid, is64) < (long long)g) lo = mid + 1;
        else hi = mid;
    }
    g_starts[g] = lo;
}

__global__ void pool_kernel(const float* __restrict__ h, int ldh)
{
    int g = blockIdx.x;
    int c = threadIdx.x;  // 256
    int s = g_starts[g], e = g_starts[g + 1];
    float sum = 0.f;
    for (int i = s; i < e; i++) sum += h[(size_t)i * ldh + c];
    float cnt = (float)(e - s);
    g_pooled[g * HD + c] = sum / fmaxf(cnt, 1.f);
}

// ---------------- driver --------------------------------------------------
extern "C" void kernel_launch(void* const* d_in, const int* in_sizes, int n_in,
                              void* d_out, int out_size)
{
    const float* x        = (const float*)d_in[0];
    const float* edge_attr= (const float*)d_in[1];
    const float* emb_w1   = (const float*)d_in[2];
    const float* emb_b1   = (const float*)d_in[3];
    const float* emb_w2   = (const float*)d_in[4];
    const float* emb_b2   = (const float*)d_in[5];
    const float* mw1      = (const float*)d_in[6];
    const float* mb1      = (const float*)d_in[7];
    const float* mw2      = (const float*)d_in[8];
    const float* mb2      = (const float*)d_in[9];
    const float* uw1      = (const float*)d_in[10];
    const float* ub1      = (const float*)d_in[11];
    const float* uw2      = (const float*)d_in[12];
    const float* ub2      = (const float*)d_in[13];
    const float* hw1      = (const float*)d_in[14];
    const float* hb1      = (const float*)d_in[15];
    const float* hw2      = (const float*)d_in[16];
    const float* hb2      = (const float*)d_in[17];
    const void* ei        = d_in[18];
    const void* batch     = d_in[19];

    float *cat0, *cat1, *tmp, *PQ, *S, *Bcat, *deg, *pooled, *htmp;
    cudaGetSymbolAddress((void**)&cat0, g_cat0);
    cudaGetSymbolAddress((void**)&cat1, g_cat1);
    cudaGetSymbolAddress((void**)&tmp, g_tmp);
    cudaGetSymbolAddress((void**)&PQ, g_PQ);
    cudaGetSymbolAddress((void**)&S, g_S);
    cudaGetSymbolAddress((void**)&Bcat, g_Bcat);
    cudaGetSymbolAddress((void**)&deg, g_deg);
    cudaGetSymbolAddress((void**)&pooled, g_pooled);
    cudaGetSymbolAddress((void**)&htmp, g_htmp);

    detect_kernel<<<1, 1>>>(ei);
    zero_kernel<<<(NN + 1023) / 1024, 1024>>>(deg, NN);
    deg_kernel<<<(NE + 255) / 256, 256>>>(ei, deg);

    dim3 blk(256);
    dim3 gN(HD / 128, (NN + 127) / 128);      // N=256 node GEMMs
    dim3 gW(2 * HD / 128, (NN + 127) / 128);  // N=512 node GEMMs

    // Embedder: h = relu(x@W1+b1)@W2+b2  -> cat0[:,0:256]
    sgemm<<<gN, blk>>>(x, NFEAT, emb_w1, emb_b1, tmp, HD, NN, NFEAT, HD, FLAG_RELU, nullptr);
    sgemm<<<gN, blk>>>(tmp, HD, emb_w2, emb_b2, cat0, 2 * HD, NN, HD, HD, 0, nullptr);

    float* cur = cat0;   // h in cols [0:256), agg written into [256:512)
    float* nxt = cat1;
    for (int l = 0; l < NL; l++) {
        const float* w1 = mw1 + (size_t)l * (2 * HD + EFEAT) * HD;
        // PQ = h @ [W1a|W1b]
        repack_kernel<<<(HD * 2 * HD + 255) / 256, 256>>>(w1, Bcat);
        sgemm<<<gW, blk>>>(cur, 2 * HD, Bcat, nullptr, PQ, 2 * HD, NN, HD, 2 * HD, 0, nullptr);
        // S = scatter_add over edges of relu(P[dst]+Q[src]+ea@W1c+b1)
        zero_kernel<<<(NN * HD + 1023) / 1024, 1024>>>(S, NN * HD);
        combine_scatter<<<NE / 4, 256>>>(PQ, edge_attr, w1 + (size_t)2 * HD * HD,
                                         mb1 + (size_t)l * HD, ei, S);
        // agg = S @ W2 + deg*b2  -> cur[:,256:512]
        sgemm<<<gN, blk>>>(S, HD, mw2 + (size_t)l * HD * HD, mb2 + (size_t)l * HD,
                           cur + HD, 2 * HD, NN, HD, HD, 0, deg);
        // update: tmp = relu([h|agg] @ uw1 + ub1)   (single K=512 GEMM)
        sgemm<<<gN, blk>>>(cur, 2 * HD, uw1 + (size_t)l * 2 * HD * HD,
                           ub1 + (size_t)l * HD, tmp, HD, NN, 2 * HD, HD, FLAG_RELU, nullptr);
        // h_new = tmp @ uw2 + ub2 -> nxt[:,0:256]
        sgemm<<<gN, blk>>>(tmp, HD, uw2 + (size_t)l * HD * HD, ub2 + (size_t)l * HD,
                           nxt, 2 * HD, NN, HD, HD, 0, nullptr);
        float* t = cur; cur = nxt; nxt = t;
    }

    // Pool + head
    starts_kernel<<<1, 128>>>(batch);
    pool_kernel<<<NG, HD>>>(cur, 2 * HD);
    sgemm<<<dim3(2, 1), blk>>>(pooled, HD, hw1, hb1, htmp, HD, NG, HD, HD, FLAG_RELU, nullptr);
    sgemm<<<dim3(1, 1), blk>>>(htmp, HD, hw2, hb2, (float*)d_out, OUTF, NG, HD, OUTF, 0, nullptr);
}

// round 5
// speedup vs baseline: 2.1547x; 1.4234x over previous
#include <cuda_runtime.h>

#define NN 20000
#define NE 320000
#define NFEAT 128
#define EFEAT 32
#define HD 256
#define OUTF 128
#define NL 4
#define NG 64

#define FLAG_RELU 1

// ---------------- scratch (static device globals; no allocations) ----------
__device__ float g_cat0[NN * 2 * HD];   // [n][0:256]=h, [n][256:512]=agg
__device__ float g_cat1[NN * 2 * HD];
__device__ float g_tmp[NN * HD];
__device__ float g_PQ[NN * 2 * HD];     // [n][0:256]=P, [n][256:512]=Q
__device__ float g_S[NN * HD];          // per-node reduced relu messages
__device__ float g_Bcat[HD * 2 * HD];   // repacked [256,512] weight for PQ GEMM
__device__ float g_deg[NN];
__device__ int g_counts[NN];
__device__ int g_cursor[NN];
__device__ int g_nstarts[NN + 1];
__device__ int g_csr_src[NE];
__device__ int g_csr_edge[NE];
__device__ float g_pooled[NG * HD];
__device__ float g_htmp[NG * HD];
__device__ int g_starts[NG + 1];
__device__ int g_is64;   // 1 if index arrays are int64, 0 if int32

// element-indexed load honoring detected dtype
__device__ __forceinline__ long long load_idx(const void* p, long long i, int is64)
{
    if (is64) return ((const long long*)p)[i];
    return (long long)(((const int*)p)[i]);
}

// Detect whether index arrays are int64 or int32 (jax x64-disabled quirk).
__global__ void detect_kernel(const void* ei)
{
    const long long* p = (const long long*)ei;
    int ok = 1;
#pragma unroll
    for (int i = 0; i < 8; i++) {
        long long v = p[i];
        if (v < 0 || v >= NN) ok = 0;
    }
    g_is64 = ok;
}

// ---------------- generic fp32 SGEMM: C[M,N] = A[M,K] @ B[K,N] -------------
// A row stride = lda, C row stride = ldc, B row-major [K,N] contiguous.
// Epilogue: +bias (optionally scaled per-row by deg), optional relu.
// Requires: K % 8 == 0, N % 128 == 0, lda/ldc % 4 == 0.
__global__ void __launch_bounds__(256, 2)
sgemm(const float* __restrict__ A, int lda,
      const float* __restrict__ B,
      const float* __restrict__ bias, float* __restrict__ C, int ldc,
      int M, int K, int N, int flags, const float* __restrict__ deg)
{
    __shared__ __align__(16) float As[8][128];
    __shared__ __align__(16) float Bs[8][128];

    const int tid = threadIdx.x;
    const int tx = tid & 15;
    const int ty = tid >> 4;
    const int bx = blockIdx.x, by = blockIdx.y;

    const int arow = tid >> 1;
    const int acol = (tid & 1) << 2;
    const int brow = tid >> 5;
    const int bcol = (tid & 31) << 2;

    const int gArow = by * 128 + arow;
    const int gBcol0 = bx * 128;

    float acc[8][8];
#pragma unroll
    for (int i = 0; i < 8; i++)
#pragma unroll
        for (int j = 0; j < 8; j++) acc[i][j] = 0.f;

    const float* Ap = A + (size_t)gArow * lda;
    const float* Bp = B + (size_t)brow * N + gBcol0 + bcol;

    for (int kt = 0; kt < K; kt += 8) {
        float4 av = make_float4(0.f, 0.f, 0.f, 0.f);
        if (gArow < M) av = *(const float4*)(Ap + kt + acol);
        As[acol + 0][arow] = av.x;
        As[acol + 1][arow] = av.y;
        As[acol + 2][arow] = av.z;
        As[acol + 3][arow] = av.w;

        float4 bv = *(const float4*)(Bp + (size_t)kt * N);
        *(float4*)&Bs[brow][bcol] = bv;
        __syncthreads();

#pragma unroll
        for (int k = 0; k < 8; k++) {
            float4 a0 = *(const float4*)&As[k][ty * 8];
            float4 a1 = *(const float4*)&As[k][ty * 8 + 4];
            float4 b0 = *(const float4*)&Bs[k][tx * 4];
            float4 b1 = *(const float4*)&Bs[k][64 + tx * 4];
            float a[8] = {a0.x, a0.y, a0.z, a0.w, a1.x, a1.y, a1.z, a1.w};
            float b[8] = {b0.x, b0.y, b0.z, b0.w, b1.x, b1.y, b1.z, b1.w};
#pragma unroll
            for (int i = 0; i < 8; i++)
#pragma unroll
                for (int j = 0; j < 8; j++)
                    acc[i][j] = fmaf(a[i], b[j], acc[i][j]);
        }
        __syncthreads();
    }

    const bool relu = (flags & FLAG_RELU) != 0;

    float bb[8];
#pragma unroll
    for (int j = 0; j < 8; j++) {
        int col = gBcol0 + ((j < 4) ? (tx * 4 + j) : (64 + tx * 4 + (j - 4)));
        bb[j] = bias ? bias[col] : 0.f;
    }

#pragma unroll
    for (int i = 0; i < 8; i++) {
        int row = by * 128 + ty * 8 + i;
        if (row >= M) continue;
        float bscale = deg ? deg[row] : 1.f;
        size_t base = (size_t)row * ldc;
        int c0 = gBcol0 + tx * 4;
        int c1 = gBcol0 + 64 + tx * 4;
        float4 v0 = make_float4(acc[i][0] + bscale * bb[0], acc[i][1] + bscale * bb[1],
                                acc[i][2] + bscale * bb[2], acc[i][3] + bscale * bb[3]);
        float4 v1 = make_float4(acc[i][4] + bscale * bb[4], acc[i][5] + bscale * bb[5],
                                acc[i][6] + bscale * bb[6], acc[i][7] + bscale * bb[7]);
        if (relu) {
            v0.x = fmaxf(v0.x, 0.f); v0.y = fmaxf(v0.y, 0.f);
            v0.z = fmaxf(v0.z, 0.f); v0.w = fmaxf(v0.w, 0.f);
            v1.x = fmaxf(v1.x, 0.f); v1.y = fmaxf(v1.y, 0.f);
            v1.z = fmaxf(v1.z, 0.f); v1.w = fmaxf(v1.w, 0.f);
        }
        *(float4*)&C[base + c0] = v0;
        *(float4*)&C[base + c1] = v1;
    }
}

// ---------------- repack W1 P|Q columns into Bcat[256][512] ----------------
__global__ void repack_kernel(const float* __restrict__ w1, float* __restrict__ Bcat)
{
    int idx = blockIdx.x * 256 + threadIdx.x;   // over 256*512
    if (idx >= HD * 2 * HD) return;
    int k = idx >> 9;
    int j = idx & 511;
    float v = (j < HD) ? w1[(size_t)k * HD + j]
                       : w1[(size_t)(HD + k) * HD + (j - HD)];
    Bcat[idx] = v;
}

// ---------------- CSR construction ----------------------------------------
__global__ void zero_int_kernel(int* __restrict__ p, int n)
{
    int i = blockIdx.x * blockDim.x + threadIdx.x;
    if (i < n) p[i] = 0;
}

__global__ void count_kernel(const void* __restrict__ ei, int* __restrict__ counts)
{
    int e = blockIdx.x * 256 + threadIdx.x;
    if (e >= NE) return;
    int d = (int)load_idx(ei, (long long)NE + e, g_is64);
    atomicAdd(&counts[d], 1);
}

// single-block exclusive scan over counts[NN] -> nstarts[NN+1]; also deg float
#define SCAN_T 1024
#define SCAN_C 20   // 1024*20 >= 20000
__global__ void scan_kernel(const int* __restrict__ counts, int* __restrict__ nstarts,
                            float* __restrict__ deg)
{
    __shared__ int part[SCAN_T];
    int t = threadIdx.x;
    int base = t * SCAN_C;
    int sum = 0;
#pragma unroll
    for (int i = 0; i < SCAN_C; i++) {
        int idx = base + i;
        if (idx < NN) sum += counts[idx];
    }
    part[t] = sum;
    __syncthreads();
    for (int off = 1; off < SCAN_T; off <<= 1) {
        int v = (t >= off) ? part[t - off] : 0;
        __syncthreads();
        part[t] += v;
        __syncthreads();
    }
    int offset = (t == 0) ? 0 : part[t - 1];
#pragma unroll
    for (int i = 0; i < SCAN_C; i++) {
        int idx = base + i;
        if (idx < NN) {
            int c = counts[idx];
            nstarts[idx] = offset;
            deg[idx] = (float)c;
            offset += c;
        }
    }
    if (t == SCAN_T - 1) nstarts[NN] = offset;
}

__global__ void fill_kernel(const void* __restrict__ ei, const int* __restrict__ nstarts,
                            int* __restrict__ cursor,
                            int* __restrict__ csr_src, int* __restrict__ csr_edge)
{
    int e = blockIdx.x * 256 + threadIdx.x;
    if (e >= NE) return;
    int is64 = g_is64;
    int s = (int)load_idx(ei, e, is64);
    int d = (int)load_idx(ei, (long long)NE + e, is64);
    int pos = nstarts[d] + atomicAdd(&cursor[d], 1);
    csr_src[pos] = s;
    csr_edge[pos] = e;
}

// ---------------- CSR combine: per-node register reduction -----------------
// block = node n, thread = channel c.
// S[n][c] = sum over incoming edges of relu(P[n][c] + Q[src][c] + ea[e]@W1c[:,c] + b1[c])
#define CHUNK 64
__global__ void __launch_bounds__(256)
combine_csr(const float* __restrict__ PQ, const float* __restrict__ ea,
            const float* __restrict__ W1c, const float* __restrict__ b1,
            const int* __restrict__ nstarts,
            const int* __restrict__ csr_src, const int* __restrict__ csr_edge,
            float* __restrict__ S)
{
    __shared__ __align__(16) float ea_s[CHUNK * EFEAT];  // 8KB
    __shared__ int src_s[CHUNK];

    const int n = blockIdx.x;
    const int c = threadIdx.x;

    // W1c column for this channel, in registers
    float w[EFEAT];
#pragma unroll
    for (int k = 0; k < EFEAT; k++) w[k] = W1c[k * HD + c];

    const float pb = PQ[(size_t)n * (2 * HD) + c] + b1[c];

    const int s0 = nstarts[n];
    const int s1 = nstarts[n + 1];
    float acc = 0.f;

    for (int base = s0; base < s1; base += CHUNK) {
        const int cnt = min(CHUNK, s1 - base);
        __syncthreads();
        for (int i = c; i < cnt; i += 256) src_s[i] = csr_src[base + i];
        for (int i = c; i < cnt * EFEAT; i += 256) {
            int j = i >> 5, k = i & 31;
            ea_s[i] = ea[(size_t)csr_edge[base + j] * EFEAT + k];
        }
        __syncthreads();

        float q = (cnt > 0) ? PQ[(size_t)src_s[0] * (2 * HD) + HD + c] : 0.f;
        for (int j = 0; j < cnt; j++) {
            float qn = (j + 1 < cnt) ? PQ[(size_t)src_s[j + 1] * (2 * HD) + HD + c] : 0.f;
            float r = 0.f;
            const float* eaj = &ea_s[j * EFEAT];
#pragma unroll
            for (int k = 0; k < EFEAT; k++) r = fmaf(eaj[k], w[k], r);
            acc += fmaxf(pb + q + r, 0.f);
            q = qn;
        }
    }
    S[(size_t)n * HD + c] = acc;
}

// ---------------- pooling -------------------------------------------------
__global__ void starts_kernel(const void* __restrict__ batch)
{
    int g = threadIdx.x;
    if (g > NG) return;
    int is64 = g_is64;
    int lo = 0, hi = NN;
    while (lo < hi) {
        int mid = (lo + hi) >> 1;
        if (load_idx(batch, mid, is64) < (long long)g) lo = mid + 1;
        else hi = mid;
    }
    g_starts[g] = lo;
}

__global__ void pool_kernel(const float* __restrict__ h, int ldh)
{
    int g = blockIdx.x;
    int c = threadIdx.x;  // 256
    int s = g_starts[g], e = g_starts[g + 1];
    float sum = 0.f;
    for (int i = s; i < e; i++) sum += h[(size_t)i * ldh + c];
    float cnt = (float)(e - s);
    g_pooled[g * HD + c] = sum / fmaxf(cnt, 1.f);
}

// ---------------- driver --------------------------------------------------
extern "C" void kernel_launch(void* const* d_in, const int* in_sizes, int n_in,
                              void* d_out, int out_size)
{
    const float* x        = (const float*)d_in[0];
    const float* edge_attr= (const float*)d_in[1];
    const float* emb_w1   = (const float*)d_in[2];
    const float* emb_b1   = (const float*)d_in[3];
    const float* emb_w2   = (const float*)d_in[4];
    const float* emb_b2   = (const float*)d_in[5];
    const float* mw1      = (const float*)d_in[6];
    const float* mb1      = (const float*)d_in[7];
    const float* mw2      = (const float*)d_in[8];
    const float* mb2      = (const float*)d_in[9];
    const float* uw1      = (const float*)d_in[10];
    const float* ub1      = (const float*)d_in[11];
    const float* uw2      = (const float*)d_in[12];
    const float* ub2      = (const float*)d_in[13];
    const float* hw1      = (const float*)d_in[14];
    const float* hb1      = (const float*)d_in[15];
    const float* hw2      = (const float*)d_in[16];
    const float* hb2      = (const float*)d_in[17];
    const void* ei        = d_in[18];
    const void* batch     = d_in[19];

    float *cat0, *cat1, *tmp, *PQ, *S, *Bcat, *deg, *pooled, *htmp;
    int *counts, *cursor, *nstarts, *csr_src, *csr_edge;
    cudaGetSymbolAddress((void**)&cat0, g_cat0);
    cudaGetSymbolAddress((void**)&cat1, g_cat1);
    cudaGetSymbolAddress((void**)&tmp, g_tmp);
    cudaGetSymbolAddress((void**)&PQ, g_PQ);
    cudaGetSymbolAddress((void**)&S, g_S);
    cudaGetSymbolAddress((void**)&Bcat, g_Bcat);
    cudaGetSymbolAddress((void**)&deg, g_deg);
    cudaGetSymbolAddress((void**)&pooled, g_pooled);
    cudaGetSymbolAddress((void**)&htmp, g_htmp);
    cudaGetSymbolAddress((void**)&counts, g_counts);
    cudaGetSymbolAddress((void**)&cursor, g_cursor);
    cudaGetSymbolAddress((void**)&nstarts, g_nstarts);
    cudaGetSymbolAddress((void**)&csr_src, g_csr_src);
    cudaGetSymbolAddress((void**)&csr_edge, g_csr_edge);

    detect_kernel<<<1, 1>>>(ei);

    // Build CSR (dst-sorted) once per launch
    zero_int_kernel<<<(NN + 1023) / 1024, 1024>>>(counts, NN);
    zero_int_kernel<<<(NN + 1023) / 1024, 1024>>>(cursor, NN);
    count_kernel<<<(NE + 255) / 256, 256>>>(ei, counts);
    scan_kernel<<<1, SCAN_T>>>(counts, nstarts, deg);
    fill_kernel<<<(NE + 255) / 256, 256>>>(ei, nstarts, cursor, csr_src, csr_edge);

    dim3 blk(256);
    dim3 gN(HD / 128, (NN + 127) / 128);      // N=256 node GEMMs
    dim3 gW(2 * HD / 128, (NN + 127) / 128);  // N=512 node GEMMs

    // Embedder: h = relu(x@W1+b1)@W2+b2  -> cat0[:,0:256]
    sgemm<<<gN, blk>>>(x, NFEAT, emb_w1, emb_b1, tmp, HD, NN, NFEAT, HD, FLAG_RELU, nullptr);
    sgemm<<<gN, blk>>>(tmp, HD, emb_w2, emb_b2, cat0, 2 * HD, NN, HD, HD, 0, nullptr);

    float* cur = cat0;   // h in cols [0:256), agg written into [256:512)
    float* nxt = cat1;
    for (int l = 0; l < NL; l++) {
        const float* w1 = mw1 + (size_t)l * (2 * HD + EFEAT) * HD;
        // PQ = h @ [W1a|W1b]
        repack_kernel<<<(HD * 2 * HD + 255) / 256, 256>>>(w1, Bcat);
        sgemm<<<gW, blk>>>(cur, 2 * HD, Bcat, nullptr, PQ, 2 * HD, NN, HD, 2 * HD, 0, nullptr);
        // S[n] = sum_{e: dst=n} relu(P[n] + Q[src] + ea@W1c + b1)   (no atomics)
        combine_csr<<<NN, 256>>>(PQ, edge_attr, w1 + (size_t)2 * HD * HD,
                                 mb1 + (size_t)l * HD, nstarts, csr_src, csr_edge, S);
        // agg = S @ W2 + deg*b2  -> cur[:,256:512]
        sgemm<<<gN, blk>>>(S, HD, mw2 + (size_t)l * HD * HD, mb2 + (size_t)l * HD,
                           cur + HD, 2 * HD, NN, HD, HD, 0, deg);
        // update: tmp = relu([h|agg] @ uw1 + ub1)   (single K=512 GEMM)
        sgemm<<<gN, blk>>>(cur, 2 * HD, uw1 + (size_t)l * 2 * HD * HD,
                           ub1 + (size_t)l * HD, tmp, HD, NN, 2 * HD, HD, FLAG_RELU, nullptr);
        // h_new = tmp @ uw2 + ub2 -> nxt[:,0:256]
        sgemm<<<gN, blk>>>(tmp, HD, uw2 + (size_t)l * HD * HD, ub2 + (size_t)l * HD,
                           nxt, 2 * HD, NN, HD, HD, 0, nullptr);
        float* t = cur; cur = nxt; nxt = t;
    }

    // Pool + head
    starts_kernel<<<1, 128>>>(batch);
    pool_kernel<<<NG, HD>>>(cur, 2 * HD);
    sgemm<<<dim3(2, 1), blk>>>(pooled, HD, hw1, hb1, htmp, HD, NG, HD, HD, FLAG_RELU, nullptr);
    sgemm<<<dim3(1, 1), blk>>>(htmp, HD, hw2, hb2, (float*)d_out, OUTF, NG, HD, OUTF, 0, nullptr);
}